// round 3
// baseline (speedup 1.0000x reference)
#include <cuda_runtime.h>
#include <math.h>

#define N_BATCH 16
#define CH 64
#define SCH 128
#define L_IN 8192
#define L_OUT 7682
#define TILE 128
#define NTH 512
#define NUM_BLOCKS 16

// Ping-pong residual buffers (allocation-free scratch).
__device__ float g_bufA[(size_t)N_BATCH * CH * L_IN];
__device__ float g_bufB[(size_t)N_BATCH * CH * L_IN];

// Duplicated weights: every scalar w stored as (w, w) so it can be used
// directly as an f32x2 operand. Layout per block:
//   dupWd[o][i][t] pair at 64-bit idx o*128 + i*2 + t   (256 floats/row)
//   dupWr[o][i]    pair at 64-bit idx o*64 + i          (128 floats/row)
//   dupWs[s][i]    pair at 64-bit idx s*64 + i          (128 floats/row)
#define WD_SZ (CH * CH * 2)        // 8192 scalars per block
#define WR_SZ (CH * CH)            // 4096
#define WS_SZ (SCH * CH)           // 8192
#define DUP_WD_BASE 0
#define DUP_WR_BASE (NUM_BLOCKS * WD_SZ * 2)                       // 262144
#define DUP_WS_BASE (DUP_WR_BASE + NUM_BLOCKS * WR_SZ * 2)         // 393216
#define DUP_TOTAL   (DUP_WS_BASE + NUM_BLOCKS * WS_SZ * 2)         // 655360
__device__ float g_wdup[DUP_TOTAL];

// Shared memory: only activations. 3 * 64 * 128 floats = 96 KB -> 2 CTAs/SM.
#define OFF_X0 0
#define OFF_X1 (CH * TILE)
#define OFF_G  (2 * CH * TILE)
#define SMEM_FLOATS (3 * CH * TILE)

typedef unsigned long long u64;

union F4U {
    float4 f;
    u64 u[2];
    float s[4];
};

__device__ __forceinline__ u64 fma2(u64 a, u64 b, u64 c) {
    u64 d;
    asm("fma.rn.f32x2 %0, %1, %2, %3;" : "=l"(d) : "l"(a), "l"(b), "l"(c));
    return d;
}

// g = tanh(y) * sigmoid(y), via a = e^{-y}:
// tanh = (1-a^2)/(1+a^2), sigmoid = 1/(1+a). Clamp keeps a^2 finite.
__device__ __forceinline__ float gated(float y) {
    float yc = fminf(fmaxf(y, -15.f), 15.f);
    float a = __expf(-yc);
    float a2 = a * a;
    return __fdividef(1.f - a2, (1.f + a2) * (1.f + a));
}

// One-shot weight duplication: out[2i] = out[2i+1] = in[i].
__global__ void dup_weights_kernel(const float* __restrict__ Wd,
                                   const float* __restrict__ Wr,
                                   const float* __restrict__ Ws)
{
    int idx = blockIdx.x * blockDim.x + threadIdx.x;
    const int nWd = NUM_BLOCKS * WD_SZ;
    const int nWr = NUM_BLOCKS * WR_SZ;
    const int nWs = NUM_BLOCKS * WS_SZ;
    float v; int base; int j;
    if (idx < nWd) { v = Wd[idx]; base = DUP_WD_BASE; j = idx; }
    else if (idx < nWd + nWr) { j = idx - nWd; v = Wr[j]; base = DUP_WR_BASE; }
    else if (idx < nWd + nWr + nWs) { j = idx - nWd - nWr; v = Ws[j]; base = DUP_WS_BASE; }
    else return;
    g_wdup[base + 2 * j]     = v;
    g_wdup[base + 2 * j + 1] = v;
}

__global__ void __launch_bounds__(NTH, 2)
wavenet_block_kernel(const float* __restrict__ src, int src_stride,
                     float* __restrict__ dst, int dst_stride,
                     const float* __restrict__ wd,   // dup, 256 floats/row
                     const float* __restrict__ wr,   // dup, 128 floats/row
                     const float* __restrict__ ws,   // dup, 128 floats/row
                     float* __restrict__ skip,
                     int Lcur, int d, int skip_off, int is_first)
{
    extern __shared__ float sm[];
    const int tid = threadIdx.x;
    const int n = blockIdx.y;
    const int l0 = blockIdx.x * TILE;
    const int Lnew = Lcur - d;

    // ---- stage the two input taps: X0[i][l]=src[l0+l], X1[i][l]=src[l0+l+d] ----
    const float* srcn = src + (size_t)n * CH * src_stride;
#pragma unroll
    for (int k = 0; k < (CH * TILE) / NTH; k++) {
        int idx = tid + k * NTH;
        int i = idx >> 7, l = idx & (TILE - 1);
        int p0 = l0 + l;
        int p1 = p0 + d;
        sm[OFF_X0 + idx] = (p0 < Lcur) ? srcn[(size_t)i * src_stride + p0] : 0.f;
        sm[OFF_X1 + idx] = (p1 < Lcur) ? srcn[(size_t)i * src_stride + p1] : 0.f;
    }
    __syncthreads();

    const int lt = (tid & 31) * 4;   // 4 consecutive positions (2 f32x2 pairs)
    const int ot = (tid >> 5) * 4;   // 4 consecutive output channels; uniform per warp

    // ================= phase 1: dilated conv (64x64x2) + gated activation =================
    u64 acc[4][2];
#pragma unroll
    for (int a = 0; a < 4; a++) { acc[a][0] = 0ull; acc[a][1] = 0ull; }

#pragma unroll 4
    for (int ii = 0; ii < CH; ii += 2) {
        F4U xa0, xb0, xa1, xb1;
        xa0.f = *(const float4*)(sm + OFF_X0 + ii * TILE + lt);
        xb0.f = *(const float4*)(sm + OFF_X1 + ii * TILE + lt);
        xa1.f = *(const float4*)(sm + OFF_X0 + (ii + 1) * TILE + lt);
        xb1.f = *(const float4*)(sm + OFF_X1 + (ii + 1) * TILE + lt);
#pragma unroll
        for (int oo = 0; oo < 4; oo++) {
            // dup layout: row (ot+oo) has 256 floats; (w_ii_t0,w_ii_t0,w_ii_t1,w_ii_t1) at ii*4
            F4U w0, w1;
            w0.f = __ldg((const float4*)(wd + (ot + oo) * 256 + ii * 4));
            w1.f = __ldg((const float4*)(wd + (ot + oo) * 256 + ii * 4 + 4));
#pragma unroll
            for (int h = 0; h < 2; h++) {
                acc[oo][h] = fma2(xa0.u[h], w0.u[0], acc[oo][h]);
                acc[oo][h] = fma2(xb0.u[h], w0.u[1], acc[oo][h]);
                acc[oo][h] = fma2(xa1.u[h], w1.u[0], acc[oo][h]);
                acc[oo][h] = fma2(xb1.u[h], w1.u[1], acc[oo][h]);
            }
        }
    }
    // gated activation -> G[o][l]
#pragma unroll
    for (int oo = 0; oo < 4; oo++) {
        F4U g;
        g.u[0] = acc[oo][0];
        g.u[1] = acc[oo][1];
#pragma unroll
        for (int ll = 0; ll < 4; ll++) g.s[ll] = gated(g.s[ll]);
        *(float4*)(sm + OFF_G + (ot + oo) * TILE + lt) = g.f;
    }
    __syncthreads();

    // ================= phase 2a: residual 1x1 conv + residual add =================
    u64 r[4][2];
#pragma unroll
    for (int oo = 0; oo < 4; oo++) {
        F4U x1;
        x1.f = *(const float4*)(sm + OFF_X1 + (ot + oo) * TILE + lt);
        r[oo][0] = x1.u[0];
        r[oo][1] = x1.u[1];
    }

#pragma unroll 4
    for (int ii = 0; ii < CH; ii += 4) {
        F4U g0, g1, g2, g3;
        g0.f = *(const float4*)(sm + OFF_G + (ii + 0) * TILE + lt);
        g1.f = *(const float4*)(sm + OFF_G + (ii + 1) * TILE + lt);
        g2.f = *(const float4*)(sm + OFF_G + (ii + 2) * TILE + lt);
        g3.f = *(const float4*)(sm + OFF_G + (ii + 3) * TILE + lt);
#pragma unroll
        for (int oo = 0; oo < 4; oo++) {
            F4U wA, wB;  // (w_ii,w_ii,w_ii+1,w_ii+1), (w_ii+2,w_ii+2,w_ii+3,w_ii+3)
            wA.f = __ldg((const float4*)(wr + (ot + oo) * 128 + ii * 2));
            wB.f = __ldg((const float4*)(wr + (ot + oo) * 128 + ii * 2 + 4));
#pragma unroll
            for (int h = 0; h < 2; h++) {
                r[oo][h] = fma2(g0.u[h], wA.u[0], r[oo][h]);
                r[oo][h] = fma2(g1.u[h], wA.u[1], r[oo][h]);
                r[oo][h] = fma2(g2.u[h], wB.u[0], r[oo][h]);
                r[oo][h] = fma2(g3.u[h], wB.u[1], r[oo][h]);
            }
        }
    }
    // direct coalesced store of residual output (warp-contiguous per row)
#pragma unroll
    for (int oo = 0; oo < 4; oo++) {
        F4U rv;
        rv.u[0] = r[oo][0];
        rv.u[1] = r[oo][1];
        float* drow = dst + ((size_t)n * CH + (ot + oo)) * dst_stride;
#pragma unroll
        for (int ll = 0; ll < 4; ll++) {
            int p = l0 + lt + ll;
            if (p < Lnew) drow[p] = rv.s[ll];
        }
    }

    // ================= phase 2b: skip 1x1 conv (128x64), two passes of 4 ch =================
    const int st = (tid >> 5) * 8;
#pragma unroll
    for (int half = 0; half < 2; half++) {
        u64 sk[4][2];
#pragma unroll
        for (int a = 0; a < 4; a++) { sk[a][0] = 0ull; sk[a][1] = 0ull; }

#pragma unroll 4
        for (int ii = 0; ii < CH; ii += 4) {
            F4U g0, g1, g2, g3;
            g0.f = *(const float4*)(sm + OFF_G + (ii + 0) * TILE + lt);
            g1.f = *(const float4*)(sm + OFF_G + (ii + 1) * TILE + lt);
            g2.f = *(const float4*)(sm + OFF_G + (ii + 2) * TILE + lt);
            g3.f = *(const float4*)(sm + OFF_G + (ii + 3) * TILE + lt);
#pragma unroll
            for (int ss = 0; ss < 4; ss++) {
                F4U wA, wB;
                const float* wrow = ws + (st + half * 4 + ss) * 128;
                wA.f = __ldg((const float4*)(wrow + ii * 2));
                wB.f = __ldg((const float4*)(wrow + ii * 2 + 4));
#pragma unroll
                for (int h = 0; h < 2; h++) {
                    sk[ss][h] = fma2(g0.u[h], wA.u[0], sk[ss][h]);
                    sk[ss][h] = fma2(g1.u[h], wA.u[1], sk[ss][h]);
                    sk[ss][h] = fma2(g2.u[h], wB.u[0], sk[ss][h]);
                    sk[ss][h] = fma2(g3.u[h], wB.u[1], sk[ss][h]);
                }
            }
        }
        // skip accumulation directly in global (one writer per element per launch)
#pragma unroll
        for (int ss = 0; ss < 4; ss++) {
            F4U sv;
            sv.u[0] = sk[ss][0];
            sv.u[1] = sk[ss][1];
            float* srow = skip + ((size_t)n * SCH + (st + half * 4 + ss)) * L_OUT;
            if (is_first) {
#pragma unroll
                for (int ll = 0; ll < 4; ll++) {
                    int p = l0 + lt + ll;
                    int j = p - skip_off;
                    if (p < Lnew && j >= 0) srow[j] = sv.s[ll];
                }
            } else {
#pragma unroll
                for (int ll = 0; ll < 4; ll++) {
                    int p = l0 + lt + ll;
                    int j = p - skip_off;
                    if (p < Lnew && j >= 0) srow[j] += sv.s[ll];
                }
            }
        }
    }
}

extern "C" void kernel_launch(void* const* d_in, const int* in_sizes, int n_in,
                              void* d_out, int out_size)
{
    const float* x  = (const float*)d_in[0];  // (16, 64, 8192)
    const float* Wd = (const float*)d_in[1];  // (16, 64, 64, 2)
    const float* Wr = (const float*)d_in[2];  // (16, 64, 64)
    const float* Ws = (const float*)d_in[3];  // (16, 128, 64)

    float* out  = (float*)d_out;                                   // (16, 64, 7682)
    float* skip = (float*)d_out + (size_t)N_BATCH * CH * L_OUT;    // (16, 128, 7682)

    float *bufA = nullptr, *bufB = nullptr, *wdup = nullptr;
    cudaGetSymbolAddress((void**)&bufA, g_bufA);
    cudaGetSymbolAddress((void**)&bufB, g_bufB);
    cudaGetSymbolAddress((void**)&wdup, g_wdup);
    cudaFuncSetAttribute(wavenet_block_kernel,
                         cudaFuncAttributeMaxDynamicSharedMemorySize,
                         SMEM_FLOATS * (int)sizeof(float));

    // duplicate all weights once per replay
    {
        int total = NUM_BLOCKS * (WD_SZ + WR_SZ + WS_SZ);
        dup_weights_kernel<<<(total + 255) / 256, 256>>>(Wd, Wr, Ws);
    }

    const int dil[NUM_BLOCKS] = {1, 2, 4, 8, 16, 32, 64, 128,
                                 1, 2, 4, 8, 16, 32, 64, 128};

    const float* src = x;
    int src_stride = L_IN;
    int Lcur = L_IN;

    for (int i = 0; i < NUM_BLOCKS; i++) {
        int d = dil[i];
        int Lnew = Lcur - d;
        float* dst;
        int dst_stride;
        if (i == NUM_BLOCKS - 1) { dst = out; dst_stride = L_OUT; }
        else                     { dst = (i & 1) ? bufB : bufA; dst_stride = L_IN; }

        dim3 grid((Lnew + TILE - 1) / TILE, N_BATCH);
        wavenet_block_kernel<<<grid, NTH, SMEM_FLOATS * sizeof(float)>>>(
            src, src_stride, dst, dst_stride,
            wdup + DUP_WD_BASE + (size_t)i * WD_SZ * 2,
            wdup + DUP_WR_BASE + (size_t)i * WR_SZ * 2,
            wdup + DUP_WS_BASE + (size_t)i * WS_SZ * 2,
            skip, Lcur, d, Lnew - L_OUT, (i == 0) ? 1 : 0);

        src = dst;
        src_stride = dst_stride;
        Lcur = Lnew;
    }
}